// round 1
// baseline (speedup 1.0000x reference)
#include <cuda_runtime.h>
#include <math.h>

// Shapes (fixed for this problem)
#define kB 4
#define kH 12
#define kS 2048
#define kD 64
#define BSv 64
#define Lv 32
#define NSTEPS 4
#define BH (kB*kH)

// ---------------- device scratch (module-load allocated) ----------------
__device__ float g_lp[(size_t)BH*BSv*Lv*Lv];      // [bh][j][l][k]
__device__ float g_rp[(size_t)BH*Lv*BSv*BSv];     // [bh][k][j][i]
__device__ float g_KR[(size_t)BH*Lv*BSv*kD];      // [bh][k][j][v]  (reused as Y at the end)
__device__ float g_LQ[(size_t)BH*BSv*Lv*kD];      // [bh][j][kk][v]
__device__ float g_r2[BH*Lv*BSv];                 // [bh][k][j]
__device__ float g_l2[BH*BSv*Lv];                 // [bh][j][k]
__device__ float g_Qs[(size_t)BH*kS*kD];          // scaled query
__device__ float g_leftF[(size_t)BH*BSv*Lv*Lv];   // final left [bh][j][l][k]
__device__ float g_eta[kH*2*NSTEPS];              // softplus(step_size)

__device__ __forceinline__ float softplusf(float x) {
    return x > 20.f ? x : log1pf(expf(x));
}

__device__ __forceinline__ float warp_allred(float v) {
    #pragma unroll
    for (int o = 16; o > 0; o >>= 1) v += __shfl_xor_sync(0xffffffffu, v, o);
    return v;
}

// ---------------- prep: Qs, lp/rp init, eta ----------------
__global__ void __launch_bounds__(256) prep_kernel(const float* __restrict__ query,
                                                   const float* __restrict__ ascale,
                                                   const float* __restrict__ ssize) {
    size_t i = (size_t)blockIdx.x * 256 + threadIdx.x;       // grid covers BH*S*D exactly
    __shared__ float s_sc;
    int h = (int)((i / ((size_t)kS * kD)) % kH);             // constant per block (S*D % 256 == 0)
    if (threadIdx.x == 0) s_sc = softplusf(ascale[h]) * rsqrtf((float)kD);
    __syncthreads();
    g_Qs[i] = query[i] * s_sc;

    size_t stride = (size_t)gridDim.x * 256;
    const size_t LPN = (size_t)BH*BSv*Lv*Lv;
    const size_t RPN = (size_t)BH*Lv*BSv*BSv;
    for (size_t t = i; t < LPN; t += stride) g_lp[t] = 0.17677669529663687f;   // 1/sqrt(32)
    for (size_t t = i; t < RPN; t += stride) g_rp[t] = 0.125f;                  // 1/sqrt(64)
    if (i < (size_t)kH*2*NSTEPS) g_eta[i] = softplusf(ssize[i]);
}

// ---------------- step-0 KR: right0 == 1/64 -> KR0 = colmean of K ----------------
__global__ void __launch_bounds__(256) init_kr_kernel(const float* __restrict__ key) {
    int bh = blockIdx.x / Lv;
    int k  = blockIdx.x % Lv;
    const float* Kt = key + ((size_t)bh*kS + (size_t)k*BSv) * kD;
    __shared__ float s_m[kD];
    int tid = threadIdx.x;
    if (tid < kD) {
        float s = 0.f;
        #pragma unroll 8
        for (int i = 0; i < BSv; i++) s += Kt[(size_t)i*kD + tid];
        s_m[tid] = s * (1.0f/64.0f);
    }
    __syncthreads();
    float* KRo = g_KR + ((size_t)(bh*Lv + k) * BSv) * kD;
    #pragma unroll
    for (int it = 0; it < (BSv*kD)/256; it++) {
        int idx = tid + it*256;
        KRo[idx] = s_m[idx & 63];
    }
    if (tid < BSv) g_r2[(bh*Lv + k)*BSv + tid] = 1.0f/64.0f;
}

// ---------------- left step: per (bh, j) ----------------
template<bool LAST>
__global__ void __launch_bounds__(256) left_step_kernel(int s) {
    __shared__ float s_lp[Lv][Lv];
    __shared__ float s_ls[Lv][Lv];
    __shared__ float s_left[Lv][Lv];
    __shared__ float s_dl[Lv][Lv];
    __shared__ float s_qT[kD][Lv + 2];     // [v][l], stride 34 (float2-aligned)
    __shared__ float s_krT[kD][Lv + 2];    // [v][k]
    __shared__ float s_invn[Lv];
    __shared__ float s_r2c[Lv];

    int bh = blockIdx.x / BSv;
    int j  = blockIdx.x % BSv;
    int h  = bh % kH;
    int tid  = threadIdx.x;
    int lane = tid & 31;
    int warp = tid >> 5;

    const size_t lp_base = ((size_t)(bh*BSv + j)) * (Lv*Lv);
    #pragma unroll
    for (int it = 0; it < 4; it++) {
        int idx = tid + it*256;
        ((float*)s_lp)[idx] = g_lp[lp_base + idx];
    }
    if (tid < Lv) s_r2c[tid] = g_r2[(bh*Lv + tid)*BSv + j];
    __syncthreads();

    // row-normalize lp over k (warp w owns rows w, w+8, w+16, w+24)
    #pragma unroll
    for (int r = 0; r < 4; r++) {
        int l = warp + r*8;
        float x  = s_lp[l][lane];
        float ss = warp_allred(x*x);
        float n  = sqrtf(ss);
        float sc = n > 0.f ? 1.0f/n : 1.0f;
        float ls = x * sc;
        s_ls[l][lane]   = ls;
        s_left[l][lane] = ls*ls;
        if (lane == 0) s_invn[l] = n > 0.f ? 1.0f/n : 0.f;
    }
    __syncthreads();

    // l2[k] = sum_l left^2
    if (tid < Lv) {
        float acc = 0.f;
        #pragma unroll
        for (int l = 0; l < Lv; l++) { float v = s_left[l][tid]; acc += v*v; }
        g_l2[(size_t)(bh*BSv + j)*Lv + tid] = acc;
    }

    // load Q_j and KR_j, transposed into smem
    const float* Qb  = g_Qs + (size_t)bh*kS*kD;
    const float* KRb = g_KR + (size_t)bh*Lv*BSv*kD;
    #pragma unroll
    for (int it = 0; it < 8; it++) {
        int idx = tid + it*256;
        int row = idx >> 6;
        int v   = idx & 63;
        s_qT[v][row]  = Qb [((size_t)(row*BSv + j))*kD + v];
        s_krT[v][row] = KRb[((size_t)(row*BSv + j))*kD + v];
    }
    __syncthreads();

    // t2l[l][k] = sum_v q[l][v]*kr[k][v]   (16x16 threads, 2x2 tiles)
    {
        int tx = tid & 15, ty = tid >> 4;
        int l0 = ty*2, k0 = tx*2;
        float a00=0.f,a01=0.f,a10=0.f,a11=0.f;
        #pragma unroll
        for (int v = 0; v < kD; v++) {
            float2 a = *(const float2*)&s_qT[v][l0];
            float2 b = *(const float2*)&s_krT[v][k0];
            a00 += a.x*b.x; a01 += a.x*b.y;
            a10 += a.y*b.x; a11 += a.y*b.y;
        }
        s_dl[l0][k0]   = a00; s_dl[l0][k0+1]   = a01;
        s_dl[l0+1][k0] = a10; s_dl[l0+1][k0+1] = a11;
    }
    __syncthreads();

    // dl = (r2*left - t2l)*2*ls ; project ; * inv_norm
    #pragma unroll
    for (int r = 0; r < 4; r++) {
        int l = warp + r*8;
        float ls = s_ls[l][lane];
        float dl = s_r2c[lane]*s_left[l][lane] - s_dl[l][lane];
        dl *= 2.f*ls;
        float dot = warp_allred(ls*dl);
        dl = (dl - ls*dot) * s_invn[l];
        s_dl[l][lane] = dl;
    }
    __syncthreads();

    // LQ[kk][v] = sum_l left[l][kk]*q[l][v]   (pre-update left)
    float* LQo = g_LQ + ((size_t)(bh*BSv + j)) * Lv * kD;
    #pragma unroll
    for (int it = 0; it < 8; it++) {
        int idx = tid + it*256;
        int kk = idx >> 6;
        int v  = idx & 63;
        float acc = 0.f;
        #pragma unroll
        for (int l = 0; l < Lv; l++)
            acc += s_left[l][kk] * s_qT[v][l];
        LQo[idx] = acc;
    }

    // update lp
    float eta = g_eta[h*(2*NSTEPS) + s];
    #pragma unroll
    for (int it = 0; it < 4; it++) {
        int idx = tid + it*256;
        float nv = ((float*)s_lp)[idx] - eta * ((float*)s_dl)[idx];
        g_lp[lp_base + idx] = nv;
        if (LAST) ((float*)s_lp)[idx] = nv;
    }
    if (LAST) {
        __syncthreads();
        #pragma unroll
        for (int r = 0; r < 4; r++) {
            int l = warp + r*8;
            float x  = s_lp[l][lane];
            float ss = warp_allred(x*x);
            float n  = sqrtf(ss);
            float sc = n > 0.f ? 1.0f/n : 1.0f;
            float v  = x*sc;
            g_leftF[lp_base + l*Lv + lane] = v*v;
        }
    }
}

// ---------------- right step: per (bh, k) ----------------
#define C_PAD 68
#define SMEM_C_FLOATS (4096*3 + 4352*2 + 192)

template<int MODE>  // 0 = update rp + compute next KR/r2 ; 1 = last step: compute Y from V
__global__ void __launch_bounds__(256) right_step_kernel(const float* __restrict__ key,
                                                         const float* __restrict__ val,
                                                         int s) {
    extern __shared__ float sm[];
    float* s_rs   = sm;                  // 64x64: rp -> rs -> rs_new
    float* s_Km   = s_rs  + 4096;        // 64x64 row-major K (or V)
    float* s_KT   = s_Km  + 4096;        // [v][i], stride 68
    float* s_LQT  = s_KT  + 4352;        // [v][j], stride 68 ; later rightT[i][j]
    float* s_t2r  = s_LQT + 4352;        // 64x64
    float* s_n    = s_t2r + 4096;        // 64
    float* s_invn = s_n    + 64;
    float* s_l2   = s_invn + 64;

    int bh = blockIdx.x / Lv;
    int k  = blockIdx.x % Lv;
    int h  = bh % kH;
    int tid  = threadIdx.x;
    int lane = tid & 31;
    int warp = tid >> 5;

    const size_t rp_base = ((size_t)(bh*Lv + k)) * (BSv*BSv);
    const float* Kt  = key + ((size_t)bh*kS + (size_t)k*BSv) * kD;
    const float* LQb = g_LQ + (size_t)bh*BSv*Lv*kD + (size_t)k*kD;

    #pragma unroll
    for (int it = 0; it < 16; it++) {
        int idx = tid + it*256;
        s_rs[idx] = g_rp[rp_base + idx];
        int row = idx >> 6, v = idx & 63;
        float kv = Kt[idx];
        s_KT[v*C_PAD + row] = kv;
        if (MODE == 0) s_Km[idx] = kv;
        s_LQT[v*C_PAD + row] = LQb[(size_t)row*(Lv*kD) + v];
    }
    if (tid < BSv) s_l2[tid] = g_l2[(size_t)(bh*BSv + tid)*Lv + k];
    __syncthreads();

    // normalize rp rows over i (warp w owns rows w, w+8, ..., lanes cover i=lane,lane+32)
    #pragma unroll
    for (int r = 0; r < 8; r++) {
        int j = warp + r*8;
        float x0 = s_rs[j*BSv + lane];
        float x1 = s_rs[j*BSv + lane + 32];
        float ss = warp_allred(x0*x0 + x1*x1);
        float n  = sqrtf(ss);
        float sc = n > 0.f ? 1.0f/n : 1.0f;
        s_rs[j*BSv + lane]      = x0*sc;
        s_rs[j*BSv + lane + 32] = x1*sc;
        if (lane == 0) { s_n[j] = n > 0.f ? n : 1.0f; s_invn[j] = n > 0.f ? 1.0f/n : 0.f; }
    }
    __syncthreads();

    // t2r[j][i] = sum_v LQ[j][v]*K[i][v]   (16x16 threads, 4x4 tiles)
    {
        int tx = tid & 15, ty = tid >> 4;
        int j0 = ty*4, i0 = tx*4;
        float acc[4][4] = {};
        #pragma unroll
        for (int v = 0; v < kD; v++) {
            float4 a4 = *(const float4*)&s_LQT[v*C_PAD + j0];
            float4 b4 = *(const float4*)&s_KT[v*C_PAD + i0];
            float a[4] = {a4.x,a4.y,a4.z,a4.w};
            float b[4] = {b4.x,b4.y,b4.z,b4.w};
            #pragma unroll
            for (int r = 0; r < 4; r++)
                #pragma unroll
                for (int c = 0; c < 4; c++)
                    acc[r][c] += a[r]*b[c];
        }
        #pragma unroll
        for (int r = 0; r < 4; r++)
            *(float4*)&s_t2r[(j0+r)*BSv + i0] =
                make_float4(acc[r][0],acc[r][1],acc[r][2],acc[r][3]);
    }
    __syncthreads();

    // dr, project, update rp, renormalize -> rs_new (in place)
    float eta = g_eta[h*(2*NSTEPS) + NSTEPS + s];
    #pragma unroll
    for (int r = 0; r < 8; r++) {
        int j = warp + r*8;
        float rs0 = s_rs[j*BSv + lane], rs1 = s_rs[j*BSv + lane + 32];
        float l2v = s_l2[j];
        float t0 = s_t2r[j*BSv + lane], t1 = s_t2r[j*BSv + lane + 32];
        float dr0 = (l2v*rs0*rs0 - t0) * 2.f * rs0;
        float dr1 = (l2v*rs1*rs1 - t1) * 2.f * rs1;
        float dot = warp_allred(rs0*dr0 + rs1*dr1);
        float invn = s_invn[j];
        dr0 = (dr0 - rs0*dot) * invn;
        dr1 = (dr1 - rs1*dot) * invn;
        float nf = s_n[j];
        float rp0 = rs0*nf - eta*dr0;
        float rp1 = rs1*nf - eta*dr1;
        if (MODE == 0) {
            g_rp[rp_base + j*BSv + lane]      = rp0;
            g_rp[rp_base + j*BSv + lane + 32] = rp1;
        }
        float ss2 = warp_allred(rp0*rp0 + rp1*rp1);
        float n2  = sqrtf(ss2);
        float sc2 = n2 > 0.f ? 1.0f/n2 : 1.0f;
        float rsn0 = rp0*sc2, rsn1 = rp1*sc2;
        s_rs[j*BSv + lane]      = rsn0;
        s_rs[j*BSv + lane + 32] = rsn1;
        if (MODE == 0) {
            float rt0 = rsn0*rsn0, rt1 = rsn1*rsn1;
            float r2s = warp_allred(rt0*rt0 + rt1*rt1);
            if (lane == 0) g_r2[(bh*Lv + k)*BSv + j] = r2s;
        }
    }
    __syncthreads();

    // rightT[i][j] = rs_new[j][i]^2 (overwrite s_LQT) ; MODE1: load V into s_Km
    #pragma unroll
    for (int it = 0; it < 16; it++) {
        int idx = tid + it*256;
        int j2 = idx >> 6, i2 = idx & 63;
        float rv = s_rs[idx];
        s_LQT[i2*C_PAD + j2] = rv*rv;
    }
    if (MODE == 1) {
        const float* Vt = val + ((size_t)bh*kS + (size_t)k*BSv) * kD;
        #pragma unroll
        for (int it = 0; it < 16; it++) {
            int idx = tid + it*256;
            s_Km[idx] = Vt[idx];
        }
    }
    __syncthreads();

    // OUT[j][v] = sum_i rightT[i][j] * Km[i][v]  -> g_KR (next KR, or Y at last step)
    float* outp = g_KR + ((size_t)(bh*Lv + k) * BSv) * kD;
    {
        int tx = tid & 15, ty = tid >> 4;
        int j0 = ty*4, v0 = tx*4;
        float acc[4][4] = {};
        #pragma unroll
        for (int i = 0; i < BSv; i++) {
            float4 a4 = *(const float4*)&s_LQT[i*C_PAD + j0];
            float4 b4 = *(const float4*)&s_Km[i*kD + v0];
            float a[4] = {a4.x,a4.y,a4.z,a4.w};
            float b[4] = {b4.x,b4.y,b4.z,b4.w};
            #pragma unroll
            for (int r = 0; r < 4; r++)
                #pragma unroll
                for (int c = 0; c < 4; c++)
                    acc[r][c] += a[r]*b[c];
        }
        #pragma unroll
        for (int r = 0; r < 4; r++)
            *(float4*)&outp[(size_t)(j0+r)*kD + v0] =
                make_float4(acc[r][0],acc[r][1],acc[r][2],acc[r][3]);
    }
}

// ---------------- final Z = left @ Y, scatter to output ----------------
__global__ void __launch_bounds__(256) zout_kernel(float* __restrict__ out) {
    __shared__ float s_left[Lv][Lv];
    __shared__ float s_y[Lv][kD];
    int bh = blockIdx.x / BSv;
    int j  = blockIdx.x % BSv;
    int tid = threadIdx.x;
    size_t lbase = ((size_t)(bh*BSv + j)) * (Lv*Lv);
    #pragma unroll
    for (int it = 0; it < 4; it++) {
        int idx = tid + it*256;
        ((float*)s_left)[idx] = g_leftF[lbase + idx];
    }
    const float* Yb = g_KR + (size_t)bh*Lv*BSv*kD + (size_t)j*kD;
    #pragma unroll
    for (int it = 0; it < 8; it++) {
        int idx = tid + it*256;
        int kk = idx >> 6, v = idx & 63;
        s_y[kk][v] = Yb[(size_t)kk*(BSv*kD) + v];
    }
    __syncthreads();
    #pragma unroll
    for (int it = 0; it < 8; it++) {
        int idx = tid + it*256;
        int l = idx >> 6, v = idx & 63;
        float acc = 0.f;
        #pragma unroll
        for (int kk = 0; kk < Lv; kk++)
            acc += s_left[l][kk] * s_y[kk][v];
        out[((size_t)bh*kS + (size_t)l*BSv + j)*kD + v] = acc;
    }
}

// ---------------- launch ----------------
extern "C" void kernel_launch(void* const* d_in, const int* in_sizes, int n_in,
                              void* d_out, int out_size) {
    (void)in_sizes; (void)n_in; (void)out_size;
    const float* q      = (const float*)d_in[0];
    const float* key    = (const float*)d_in[1];
    const float* val    = (const float*)d_in[2];
    const float* ascale = (const float*)d_in[3];
    const float* ssz    = (const float*)d_in[4];
    float* out = (float*)d_out;

    const size_t SMEM_C = (size_t)SMEM_C_FLOATS * sizeof(float);
    cudaFuncSetAttribute(right_step_kernel<0>, cudaFuncAttributeMaxDynamicSharedMemorySize, (int)SMEM_C);
    cudaFuncSetAttribute(right_step_kernel<1>, cudaFuncAttributeMaxDynamicSharedMemorySize, (int)SMEM_C);

    int nq_blocks = (BH*kS*kD) / 256;
    prep_kernel<<<nq_blocks, 256>>>(q, ascale, ssz);
    init_kr_kernel<<<BH*Lv, 256>>>(key);
    for (int s = 0; s < NSTEPS; s++) {
        if (s < NSTEPS-1) {
            left_step_kernel<false><<<BH*BSv, 256>>>(s);
            right_step_kernel<0><<<BH*Lv, 256, SMEM_C>>>(key, val, s);
        } else {
            left_step_kernel<true><<<BH*BSv, 256>>>(s);
            right_step_kernel<1><<<BH*Lv, 256, SMEM_C>>>(key, val, s);
        }
    }
    zout_kernel<<<BH*BSv, 256>>>(out);
}